// round 16
// baseline (speedup 1.0000x reference)
#include <cuda_runtime.h>
#include <cuda_fp16.h>
#include <math.h>

// Problem constants
#define Bz   2
#define Sz   1024
#define Dz   1024
#define Hz   16
#define Lz   4
#define Vz   32000
#define DKz  64
#define BSz  (Bz*Sz)   // 2048

#define AST  40        // smem k-stride (halves): 80B rows, LDSM conflict-free
#define FST  72        // flash smem stride (halves): 144B rows, LDSM conflict-free

// ---------------------------------------------------------------------------
// Scratch (static device globals; no allocation anywhere)
// ---------------------------------------------------------------------------
__device__ __align__(256) float  g_x [BSz*Dz];
__device__ __align__(256) __half g_xh[BSz*Dz];
__device__ __align__(256) __half g_xl[BSz*Dz];
__device__ __align__(256) __half g_hh[(long long)BSz*3*Dz];   // qkv split hi
__device__ __align__(256) __half g_hl[(long long)BSz*3*Dz];   // qkv split lo
__device__ __align__(256) __half g_oh[BSz*Dz];
__device__ __align__(256) __half g_ol[BSz*Dz];
__device__ __align__(256) float  g_o2[BSz*Dz];
__device__ __align__(256) float  g_h2[BSz*2*Dz];
// weight hi/lo, TRANSPOSED to [N][K]
__device__ __align__(256) __half g_qkh[(long long)Lz*3*Dz*Dz];
__device__ __align__(256) __half g_qkl[(long long)Lz*3*Dz*Dz];
__device__ __align__(256) __half g_owh[(long long)Lz*Dz*Dz];
__device__ __align__(256) __half g_owl[(long long)Lz*Dz*Dz];
__device__ __align__(256) __half g_mwh[(long long)Lz*2*Dz*Dz];
__device__ __align__(256) __half g_mwl[(long long)Lz*2*Dz*Dz];
__device__ __align__(256) __half g_pwh[(long long)Vz*Dz];   // proj: hi only

// ---------------------------------------------------------------------------
// helpers
// ---------------------------------------------------------------------------
__device__ __forceinline__ void split1(float v, __half& h, __half& l)
{
    h = __float2half_rn(v);
    l = __float2half_rn(v - __half2float(h));
}
__device__ __forceinline__ unsigned packh2(__half a, __half b)
{
    __half2 t = __halves2half2(a, b);
    return *reinterpret_cast<unsigned*>(&t);
}
__device__ __forceinline__ void cpa16(void* dst, const void* src)
{
    unsigned d = (unsigned)__cvta_generic_to_shared(dst);
    asm volatile("cp.async.cg.shared.global [%0], [%1], 16;\n" :: "r"(d), "l"(src));
}
__device__ __forceinline__ void cpcommit()
{
    asm volatile("cp.async.commit_group;\n");
}
__device__ __forceinline__ void mma16816(float* c, const unsigned* a, const unsigned* b)
{
    asm volatile(
        "mma.sync.aligned.m16n8k16.row.col.f32.f16.f16.f32 "
        "{%0,%1,%2,%3}, {%4,%5,%6,%7}, {%8,%9}, {%0,%1,%2,%3};\n"
        : "+f"(c[0]), "+f"(c[1]), "+f"(c[2]), "+f"(c[3])
        : "r"(a[0]), "r"(a[1]), "r"(a[2]), "r"(a[3]), "r"(b[0]), "r"(b[1]));
}
__device__ __forceinline__ void ldsm4(unsigned* r, const void* p)
{
    unsigned a = (unsigned)__cvta_generic_to_shared(p);
    asm volatile("ldmatrix.sync.aligned.m8n8.x4.shared.b16 {%0,%1,%2,%3}, [%4];\n"
        : "=r"(r[0]), "=r"(r[1]), "=r"(r[2]), "=r"(r[3]) : "r"(a));
}
__device__ __forceinline__ void ldsm4t(unsigned* r, const void* p)
{
    unsigned a = (unsigned)__cvta_generic_to_shared(p);
    asm volatile("ldmatrix.sync.aligned.m8n8.x4.trans.shared.b16 {%0,%1,%2,%3}, [%4];\n"
        : "=r"(r[0]), "=r"(r[1]), "=r"(r[2]), "=r"(r[3]) : "r"(a));
}
__device__ __forceinline__ float warp8_sum(float v, float* red, int tid)
{
    #pragma unroll
    for (int o = 16; o; o >>= 1) v += __shfl_xor_sync(0xffffffffu, v, o);
    if ((tid & 31) == 0) red[tid >> 5] = v;
    __syncthreads();
    float r = (red[0] + red[1]) + (red[2] + red[3])
            + (red[4] + red[5]) + (red[6] + red[7]);
    __syncthreads();
    return r;
}

// ---------------------------------------------------------------------------
// Weight transpose + split: W[K,N] f32 -> T_hi (+T_lo) [N,K].
// Packed uint2 stores on the transposed side (4 halves per store).
// ---------------------------------------------------------------------------
__global__ void __launch_bounds__(256)
k_wsplit(const float* __restrict__ W, __half* __restrict__ Th, __half* __restrict__ Tl,
         int K, int N)
{
    __shared__ float t[32][33];
    const long long zo = (long long)blockIdx.z * K * N;
    W  += zo; Th += zo; if (Tl) Tl += zo;
    const int n0 = blockIdx.x * 32, k0 = blockIdx.y * 32;
    const int tid = threadIdx.x;
    const int tx = tid & 31, ty = tid >> 5;
    #pragma unroll
    for (int p = 0; p < 4; p++)
        t[ty + 8*p][tx] = W[(long long)(k0 + ty + 8*p) * N + n0 + tx];
    __syncthreads();

    // packed write: thread -> (n = tid>>3, k group = (tid&7)*4)
    const int n  = tid >> 3;
    const int kg = (tid & 7) * 4;
    float v0 = t[kg    ][n], v1 = t[kg + 1][n];
    float v2 = t[kg + 2][n], v3 = t[kg + 3][n];
    __half h0,l0,h1,l1,h2,l2,h3,l3;
    split1(v0,h0,l0); split1(v1,h1,l1); split1(v2,h2,l2); split1(v3,h3,l3);
    const long long o = (long long)(n0 + n) * K + k0 + kg;
    *(uint2*)&Th[o] = make_uint2(packh2(h0,h1), packh2(h2,h3));
    if (Tl) *(uint2*)&Tl[o] = make_uint2(packh2(l0,l1), packh2(l2,l3));
}

// ---------------------------------------------------------------------------
// Embedding (writes float + hi/lo)
// ---------------------------------------------------------------------------
__global__ void k_embed(const int* __restrict__ tok,
                        const float* __restrict__ emb,
                        const float* __restrict__ pos,
                        float* __restrict__ x,
                        __half* __restrict__ xh, __half* __restrict__ xl)
{
    int row = blockIdx.x;
    int s   = row % Sz;
    long long t = tok[row];
    const float* e = emb + t * Dz;
    const float* p = pos + (long long)s * Dz;
    long long o = (long long)row * Dz;
    for (int d = threadIdx.x; d < Dz; d += blockDim.x) {
        float v = e[d] + p[d];
        x[o + d] = v;
        __half h, l; split1(v, h, l);
        xh[o + d] = h; xl[o + d] = l;
    }
}

// ---------------------------------------------------------------------------
// Fused flash attention (causal). One CTA = 128 q-rows of one (batch, head).
// Pre-split inputs; pure-copy smem fills; PV via ldmatrix.trans.
// K/V tiles DOUBLE-BUFFERED: fill(kt+1) issued before waiting on fill(kt),
// wait_group 1 allows one fill in flight (sgemm prefetch discipline).
// ---------------------------------------------------------------------------
__global__ void __launch_bounds__(256)
k_flash(const __half* __restrict__ Hh, const __half* __restrict__ Hl,
        __half* __restrict__ Oh, __half* __restrict__ Ol)
{
    const int z = blockIdx.z, b = z >> 4, head = z & 15;
    const int bx = blockIdx.x;
    const int qt = (bx < 4) ? (7 - bx) : (bx - 4);   // pair-balanced map
    const int bq = qt * 128;

    extern __shared__ __half fsm[];
    __half (*Qh)[FST] = (__half(*)[FST])fsm;
    __half (*Ql)[FST] = Qh + 128;
    __half* kvbase = fsm + 2 * 128 * FST;
    constexpr int SS = 4 * 64 * FST;   // halves per K/V stage

    const int tid = threadIdx.x, warp = tid >> 5, lane = tid & 31;
    const int g = lane >> 2, tg = lane & 3;
    const int lrow = lane & 15, lk = (lane >> 4) << 3;

    const long long base = (long long)b * Sz * 3 * Dz + head * DKz;
    const __half* Qgh = Hh + base;
    const __half* Qgl = Hl + base;
    const __half* Kgh = Qgh + Dz;
    const __half* Kgl = Qgl + Dz;
    const __half* Vgh = Qgh + 2 * Dz;
    const __half* Vgl = Qgl + 2 * Dz;

    // Q tile copy (one cp.async group)
    #pragma unroll
    for (int i = 0; i < 4; i++) {
        int u = tid + i * 256;
        int r = u >> 3, j = u & 7;
        long long off = (long long)(bq + r) * 3 * Dz + 8 * j;
        cpa16(&Qh[r][8 * j], Qgh + off);
        cpa16(&Ql[r][8 * j], Qgl + off);
    }
    cpcommit();

    auto fillkv = [&](int st, int bk) {
        __half (*Kh)[FST]  = (__half(*)[FST])(kvbase + st * SS);
        __half (*Kl)[FST]  = Kh + 64;
        __half (*Vsh)[FST] = Kl + 64;
        __half (*Vsl)[FST] = Vsh + 64;
        #pragma unroll
        for (int i = 0; i < 2; i++) {
            int u = tid + i * 256;
            int r = u >> 3, j = u & 7;
            long long off = (long long)(bk + r) * 3 * Dz + 8 * j;
            cpa16(&Kh[r][8 * j],  Kgh + off);
            cpa16(&Kl[r][8 * j],  Kgl + off);
            cpa16(&Vsh[r][8 * j], Vgh + off);
            cpa16(&Vsl[r][8 * j], Vgl + off);
        }
    };

    float m0 = -1e30f, m1 = -1e30f, l0s = 0.f, l1s = 0.f;
    float acc[8][4];
    #pragma unroll
    for (int nt = 0; nt < 8; nt++)
        #pragma unroll
        for (int i = 0; i < 4; i++) acc[nt][i] = 0.f;

    const int r0 = bq + warp * 16 + g, r1 = r0 + 8;
    const int KTILES = 2 * qt + 2;

    fillkv(0, 0);
    cpcommit();

    for (int kt = 0; kt < KTILES; kt++) {
        const int bk = kt * 64;
        const int st = kt & 1;

        if (kt + 1 < KTILES) fillkv(st ^ 1, (kt + 1) * 64);
        cpcommit();                                 // one group per iter
        asm volatile("cp.async.wait_group 1;\n");   // fill(kt) (and Q) done
        __syncthreads();

        __half (*Kh)[FST]  = (__half(*)[FST])(kvbase + st * SS);
        __half (*Kl)[FST]  = Kh + 64;
        __half (*Vsh)[FST] = Kl + 64;
        __half (*Vsl)[FST] = Vsh + 64;

        // S = Q K^T (3-term split)
        float s[8][4];
        #pragma unroll
        for (int nt = 0; nt < 8; nt++)
            #pragma unroll
            for (int i = 0; i < 4; i++) s[nt][i] = 0.f;

        #pragma unroll
        for (int c = 0; c < 4; c++) {
            unsigned ah[4], al[4], bh[8][2], bl[8][2];
            ldsm4(ah, &Qh[warp*16 + lrow][c*16 + lk]);
            ldsm4(al, &Ql[warp*16 + lrow][c*16 + lk]);
            #pragma unroll
            for (int ng = 0; ng < 4; ng++) {
                unsigned q[4];
                ldsm4(q, &Kh[ng*16 + lrow][c*16 + lk]);
                bh[2*ng][0]=q[0]; bh[2*ng+1][0]=q[1]; bh[2*ng][1]=q[2]; bh[2*ng+1][1]=q[3];
                ldsm4(q, &Kl[ng*16 + lrow][c*16 + lk]);
                bl[2*ng][0]=q[0]; bl[2*ng+1][0]=q[1]; bl[2*ng][1]=q[2]; bl[2*ng+1][1]=q[3];
            }
            #pragma unroll
            for (int nt = 0; nt < 8; nt++) {
                mma16816(s[nt], ah, bh[nt]);
                mma16816(s[nt], ah, bl[nt]);
                mma16816(s[nt], al, bh[nt]);
            }
        }

        if (kt >= 2*qt) {
            #pragma unroll
            for (int nt = 0; nt < 8; nt++) {
                int c0 = bk + nt*8 + 2*tg, c1 = c0 + 1;
                s[nt][0] = (c0 <= r0) ? s[nt][0]*0.125f : -1e30f;
                s[nt][1] = (c1 <= r0) ? s[nt][1]*0.125f : -1e30f;
                s[nt][2] = (c0 <= r1) ? s[nt][2]*0.125f : -1e30f;
                s[nt][3] = (c1 <= r1) ? s[nt][3]*0.125f : -1e30f;
            }
        } else {
            #pragma unroll
            for (int nt = 0; nt < 8; nt++)
                #pragma unroll
                for (int i = 0; i < 4; i++) s[nt][i] *= 0.125f;
        }

        float tm0 = -1e30f, tm1 = -1e30f;
        #pragma unroll
        for (int nt = 0; nt < 8; nt++) {
            tm0 = fmaxf(tm0, fmaxf(s[nt][0], s[nt][1]));
            tm1 = fmaxf(tm1, fmaxf(s[nt][2], s[nt][3]));
        }
        tm0 = fmaxf(tm0, __shfl_xor_sync(0xffffffffu, tm0, 1));
        tm0 = fmaxf(tm0, __shfl_xor_sync(0xffffffffu, tm0, 2));
        tm1 = fmaxf(tm1, __shfl_xor_sync(0xffffffffu, tm1, 1));
        tm1 = fmaxf(tm1, __shfl_xor_sync(0xffffffffu, tm1, 2));
        const float mn0 = fmaxf(m0, tm0), mn1 = fmaxf(m1, tm1);
        const float al0 = __expf(m0 - mn0), al1 = __expf(m1 - mn1);

        float rs0 = 0.f, rs1 = 0.f;
        unsigned pa[4][4];
        #pragma unroll
        for (int c = 0; c < 4; c++) {
            float p00 = __expf(s[2*c  ][0] - mn0), p01 = __expf(s[2*c  ][1] - mn0);
            float p10 = __expf(s[2*c  ][2] - mn1), p11 = __expf(s[2*c  ][3] - mn1);
            float p02 = __expf(s[2*c+1][0] - mn0), p03 = __expf(s[2*c+1][1] - mn0);
            float p12 = __expf(s[2*c+1][2] - mn1), p13 = __expf(s[2*c+1][3] - mn1);
            rs0 += (p00 + p01) + (p02 + p03);
            rs1 += (p10 + p11) + (p12 + p13);
            pa[c][0] = packh2(__float2half_rn(p00), __float2half_rn(p01));
            pa[c][1] = packh2(__float2half_rn(p10), __float2half_rn(p11));
            pa[c][2] = packh2(__float2half_rn(p02), __float2half_rn(p03));
            pa[c][3] = packh2(__float2half_rn(p12), __float2half_rn(p13));
        }
        rs0 += __shfl_xor_sync(0xffffffffu, rs0, 1);
        rs0 += __shfl_xor_sync(0xffffffffu, rs0, 2);
        rs1 += __shfl_xor_sync(0xffffffffu, rs1, 1);
        rs1 += __shfl_xor_sync(0xffffffffu, rs1, 2);
        l0s = l0s * al0 + rs0;
        l1s = l1s * al1 + rs1;
        m0 = mn0; m1 = mn1;

        #pragma unroll
        for (int nt = 0; nt < 8; nt++) {
            acc[nt][0] *= al0; acc[nt][1] *= al0;
            acc[nt][2] *= al1; acc[nt][3] *= al1;
        }

        #pragma unroll
        for (int c = 0; c < 4; c++) {
            unsigned bh[8][2], bl[8][2];
            #pragma unroll
            for (int ng = 0; ng < 4; ng++) {
                unsigned q[4];
                ldsm4t(q, &Vsh[c*16 + lrow][ng*16 + lk]);
                bh[2*ng][0]=q[0]; bh[2*ng][1]=q[1]; bh[2*ng+1][0]=q[2]; bh[2*ng+1][1]=q[3];
                ldsm4t(q, &Vsl[c*16 + lrow][ng*16 + lk]);
                bl[2*ng][0]=q[0]; bl[2*ng][1]=q[1]; bl[2*ng+1][0]=q[2]; bl[2*ng+1][1]=q[3];
            }
            #pragma unroll
            for (int nt = 0; nt < 8; nt++) {
                mma16816(acc[nt], pa[c], bh[nt]);
                mma16816(acc[nt], pa[c], bl[nt]);
            }
        }
        __syncthreads();   // protect stage st before iteration kt+1 refills it
    }

    const float il0 = 1.f / l0s, il1 = 1.f / l1s;
    const long long gr0 = (long long)b * Sz + r0;
    const long long gr1 = gr0 + 8;
    #pragma unroll
    for (int nt = 0; nt < 8; nt++) {
        int col = head * 64 + nt * 8 + 2 * tg;
        __half h0, lo0, h1, lo1;
        split1(acc[nt][0] * il0, h0, lo0); split1(acc[nt][1] * il0, h1, lo1);
        *(unsigned*)&Oh[gr0 * Dz + col] = packh2(h0, h1);
        *(unsigned*)&Ol[gr0 * Dz + col] = packh2(lo0, lo1);
        split1(acc[nt][2] * il1, h0, lo0); split1(acc[nt][3] * il1, h1, lo1);
        *(unsigned*)&Oh[gr1 * Dz + col] = packh2(h0, h1);
        *(unsigned*)&Ol[gr1 * Dz + col] = packh2(lo0, lo1);
    }
}

// ---------------------------------------------------------------------------
// Split-fp16 GEMM: ldmatrix fragments, 2-stage cp.async pipeline.
// TERMS=3: Ah*Bh + Ah*Bl + Al*Bh.  TERMS=1: Ah*Bh.
// OUTH: write split hi/lo (Ch/Cl) instead of float Cf.
// ---------------------------------------------------------------------------
template<int BN, int TERMS, bool OUTH>
__global__ void __launch_bounds__(256)
sgemm(const __half* __restrict__ Ah, const __half* __restrict__ Al, int lda,
      const __half* __restrict__ Bh, const __half* __restrict__ Bl, int ldb,
      float* __restrict__ Cf, __half* __restrict__ Ch, __half* __restrict__ Cl,
      int ldc, const float* __restrict__ bias, int K)
{
    constexpr int BM = 128, BK = 32;
    constexpr int WN = BN / 2;
    constexpr int NT = WN / 8;
    constexpr int NG = WN / 16;
    constexpr int STG = (TERMS == 3 ? (2*BM + 2*BN) : (BM + BN)) * AST;

    extern __shared__ __half smem_dyn[];

    const int bm = blockIdx.x * BM;
    const int bn = blockIdx.y * BN;
    const int tid = threadIdx.x, warp = tid >> 5, lane = tid & 31;
    const int g = lane >> 2, tg = lane & 3;
    const int wm = warp >> 1, wn = warp & 1;
    const int lrow = lane & 15;
    const int lk   = (lane >> 4) << 3;

    const int KT = K / BK;

    float acc[2][NT][4];
    #pragma unroll
    for (int mt = 0; mt < 2; mt++)
        #pragma unroll
        for (int nt = 0; nt < NT; nt++)
            #pragma unroll
            for (int i = 0; i < 4; i++) acc[mt][nt][i] = 0.f;

    auto fill = [&](int st, int k0) {
        __half* sa_h = smem_dyn + st * STG;
        __half* sa_l = sa_h + BM * AST;
        __half* sb_h = sa_h + (TERMS == 3 ? 2 : 1) * BM * AST;
        __half* sb_l = sb_h + BN * AST;
        #pragma unroll
        for (int i = 0; i < (BM * BK / 8) / 256; i++) {
            int u = tid + i * 256;
            int row = u >> 2, j = u & 3;
            long long off = (long long)(bm + row) * lda + k0 + 8 * j;
            cpa16(sa_h + row * AST + 8 * j, Ah + off);
            if (TERMS == 3) cpa16(sa_l + row * AST + 8 * j, Al + off);
        }
        #pragma unroll
        for (int i = 0; i < (BN * BK / 8) / 256; i++) {
            int u = tid + i * 256;
            int row = u >> 2, j = u & 3;
            long long off = (long long)(bn + row) * ldb + k0 + 8 * j;
            cpa16(sb_h + row * AST + 8 * j, Bh + off);
            if (TERMS == 3) cpa16(sb_l + row * AST + 8 * j, Bl + off);
        }
    };

    fill(0, 0);
    cpcommit();

    for (int kt = 0; kt < KT; kt++) {
        const int st = kt & 1;
        if (kt + 1 < KT) fill(st ^ 1, (kt + 1) * BK);
        cpcommit();
        asm volatile("cp.async.wait_group 1;\n");
        __syncthreads();

        const __half* sa_h = smem_dyn + st * STG;
        const __half* sa_l = sa_h + BM * AST;
        const __half* sb_h = sa_h + (TERMS == 3 ? 2 : 1) * BM * AST;
        const __half* sb_l = sb_h + BN * AST;

        #pragma unroll
        for (int ks = 0; ks < BK; ks += 16) {
            unsigned ah[2][4], al[2][4], bh[NT][2], bl[NT][2];
            #pragma unroll
            for (int mt = 0; mt < 2; mt++) {
                const int r = wm * 32 + mt * 16 + lrow;
                ldsm4(ah[mt], sa_h + r * AST + ks + lk);
                if (TERMS == 3) ldsm4(al[mt], sa_l + r * AST + ks + lk);
            }
            #pragma unroll
            for (int ng = 0; ng < NG; ng++) {
                const int c = wn * WN + ng * 16 + lrow;
                unsigned q[4];
                ldsm4(q, sb_h + c * AST + ks + lk);
                bh[2*ng][0] = q[0]; bh[2*ng+1][0] = q[1];
                bh[2*ng][1] = q[2]; bh[2*ng+1][1] = q[3];
                if (TERMS == 3) {
                    ldsm4(q, sb_l + c * AST + ks + lk);
                    bl[2*ng][0] = q[0]; bl[2*ng+1][0] = q[1];
                    bl[2*ng][1] = q[2]; bl[2*ng+1][1] = q[3];
                }
            }
            #pragma unroll
            for (int mt = 0; mt < 2; mt++)
                #pragma unroll
                for (int nt = 0; nt < NT; nt++) {
                    mma16816(acc[mt][nt], ah[mt], bh[nt]);
                    if (TERMS == 3) {
                        mma16816(acc[mt][nt], ah[mt], bl[nt]);
                        mma16816(acc[mt][nt], al[mt], bh[nt]);
                    }
                }
        }
        __syncthreads();
    }

    #pragma unroll
    for (int nt = 0; nt < NT; nt++) {
        int col = bn + wn * WN + nt * 8 + 2 * tg;
        float2 bv = *(const float2*)&bias[col];
        #pragma unroll
        for (int mt = 0; mt < 2; mt++) {
            int row = bm + wm * 32 + mt * 16 + g;
            float v00 = acc[mt][nt][0] + bv.x, v01 = acc[mt][nt][1] + bv.y;
            float v10 = acc[mt][nt][2] + bv.x, v11 = acc[mt][nt][3] + bv.y;
            if (OUTH) {
                __half h0, h1, l0, l1;
                split1(v00, h0, l0); split1(v01, h1, l1);
                *(unsigned*)&Ch[(long long)row * ldc + col] = packh2(h0, h1);
                *(unsigned*)&Cl[(long long)row * ldc + col] = packh2(l0, l1);
                split1(v10, h0, l0); split1(v11, h1, l1);
                *(unsigned*)&Ch[(long long)(row + 8) * ldc + col] = packh2(h0, h1);
                *(unsigned*)&Cl[(long long)(row + 8) * ldc + col] = packh2(l0, l1);
            } else {
                *(float2*)&Cf[(long long)row * ldc + col] = make_float2(v00, v01);
                *(float2*)&Cf[(long long)(row + 8) * ldc + col] = make_float2(v10, v11);
            }
        }
    }
}

// ---------------------------------------------------------------------------
// Vectorized LN kernels: 1024 = 256 threads x float4, values in registers.
// ---------------------------------------------------------------------------
__global__ void __launch_bounds__(256)
k_add_ln(const float* __restrict__ a, float* __restrict__ x,
         __half* __restrict__ xh, __half* __restrict__ xl,
         const float* __restrict__ gam, const float* __restrict__ bet)
{
    const long long row = blockIdx.x;
    const int tid = threadIdx.x;
    __shared__ float red[8];

    const float4* a4 = (const float4*)(a + row * Dz);
    float4*       x4 = (float4*)(x + row * Dz);

    float4 av = a4[tid], xv = x4[tid];
    float4 v;
    v.x = av.x + xv.x; v.y = av.y + xv.y; v.z = av.z + xv.z; v.w = av.w + xv.w;

    float s = (v.x + v.y) + (v.z + v.w);
    const float mean = warp8_sum(s, red, tid) * (1.f / Dz);

    float dx = v.x - mean, dy = v.y - mean, dz = v.z - mean, dw = v.w - mean;
    float s2 = (dx*dx + dy*dy) + (dz*dz + dw*dw);
    const float var = warp8_sum(s2, red, tid) * (1.f / Dz);
    const float inv = rsqrtf(var + 1e-5f);

    float4 gv = *(const float4*)(gam + tid*4);
    float4 bv = *(const float4*)(bet + tid*4);
    float4 y;
    y.x = dx * inv * gv.x + bv.x;
    y.y = dy * inv * gv.y + bv.y;
    y.z = dz * inv * gv.z + bv.z;
    y.w = dw * inv * gv.w + bv.w;
    x4[tid] = y;

    __half h0,l0,h1,l1,h2,l2,h3,l3;
    split1(y.x,h0,l0); split1(y.y,h1,l1); split1(y.z,h2,l2); split1(y.w,h3,l3);
    *(uint2*)&xh[row * Dz + tid*4] = make_uint2(packh2(h0,h1), packh2(h2,h3));
    *(uint2*)&xl[row * Dz + tid*4] = make_uint2(packh2(l0,l1), packh2(l2,l3));
}

__global__ void __launch_bounds__(256)
k_geglu_ln(const float* __restrict__ h2, float* __restrict__ x,
           __half* __restrict__ xh, __half* __restrict__ xl,
           const float* __restrict__ gam, const float* __restrict__ bet)
{
    const long long row = blockIdx.x;
    const int tid = threadIdx.x;
    __shared__ float red[8];

    const float4* a4 = (const float4*)(h2 + row * 2 * Dz);
    const float4* g4 = (const float4*)(h2 + row * 2 * Dz + Dz);

    float4 av = a4[tid], gg = g4[tid];
    float4 v;
    v.x = av.x * (0.5f * gg.x * (1.f + erff(gg.x * 0.70710678118654752f)));
    v.y = av.y * (0.5f * gg.y * (1.f + erff(gg.y * 0.70710678118654752f)));
    v.z = av.z * (0.5f * gg.z * (1.f + erff(gg.z * 0.70710678118654752f)));
    v.w = av.w * (0.5f * gg.w * (1.f + erff(gg.w * 0.70710678118654752f)));

    float s = (v.x + v.y) + (v.z + v.w);
    const float mean = warp8_sum(s, red, tid) * (1.f / Dz);

    float dx = v.x - mean, dy = v.y - mean, dz = v.z - mean, dw = v.w - mean;
    float s2 = (dx*dx + dy*dy) + (dz*dz + dw*dw);
    const float var = warp8_sum(s2, red, tid) * (1.f / Dz);
    const float inv = rsqrtf(var + 1e-5f);

    float4 gv = *(const float4*)(gam + tid*4);
    float4 bv = *(const float4*)(bet + tid*4);
    float4 y;
    y.x = dx * inv * gv.x + bv.x;
    y.y = dy * inv * gv.y + bv.y;
    y.z = dz * inv * gv.z + bv.z;
    y.w = dw * inv * gv.w + bv.w;
    *(float4*)(x + row * Dz + tid*4) = y;

    __half h0,l0,h1,l1,h2_,l2,h3,l3;
    split1(y.x,h0,l0); split1(y.y,h1,l1); split1(y.z,h2_,l2); split1(y.w,h3,l3);
    *(uint2*)&xh[row * Dz + tid*4] = make_uint2(packh2(h0,h1), packh2(h2_,h3));
    *(uint2*)&xl[row * Dz + tid*4] = make_uint2(packh2(l0,l1), packh2(l2,l3));
}

// ---------------------------------------------------------------------------
// Driver
// ---------------------------------------------------------------------------
extern "C" void kernel_launch(void* const* d_in, const int* in_sizes, int n_in,
                              void* d_out, int out_size)
{
    (void)in_sizes; (void)n_in; (void)out_size;
    const int*   tokens = (const int*)  d_in[0];
    const float* emb    = (const float*)d_in[2];
    const float* pos    = (const float*)d_in[3];
    const float* qkv_w  = (const float*)d_in[4];
    const float* qkv_b  = (const float*)d_in[5];
    const float* out_w  = (const float*)d_in[6];
    const float* out_b  = (const float*)d_in[7];
    const float* ln1_g  = (const float*)d_in[8];
    const float* ln1_b  = (const float*)d_in[9];
    const float* mlp_w  = (const float*)d_in[10];
    const float* mlp_b  = (const float*)d_in[11];
    const float* ln2_g  = (const float*)d_in[12];
    const float* ln2_b  = (const float*)d_in[13];
    const float* proj_w = (const float*)d_in[14];
    const float* proj_b = (const float*)d_in[15];
    float* out = (float*)d_out;

    float *x, *o2, *h2;
    __half *xh, *xl, *hh, *hl, *oh, *ol;
    __half *qkh, *qkl, *owh, *owl, *mwh, *mwl, *pwh;
    cudaGetSymbolAddress((void**)&x,  g_x);
    cudaGetSymbolAddress((void**)&xh, g_xh);
    cudaGetSymbolAddress((void**)&xl, g_xl);
    cudaGetSymbolAddress((void**)&hh, g_hh);
    cudaGetSymbolAddress((void**)&hl, g_hl);
    cudaGetSymbolAddress((void**)&oh, g_oh);
    cudaGetSymbolAddress((void**)&ol, g_ol);
    cudaGetSymbolAddress((void**)&o2, g_o2);
    cudaGetSymbolAddress((void**)&h2, g_h2);
    cudaGetSymbolAddress((void**)&qkh, g_qkh);
    cudaGetSymbolAddress((void**)&qkl, g_qkl);
    cudaGetSymbolAddress((void**)&owh, g_owh);
    cudaGetSymbolAddress((void**)&owl, g_owl);
    cudaGetSymbolAddress((void**)&mwh, g_mwh);
    cudaGetSymbolAddress((void**)&mwl, g_mwl);
    cudaGetSymbolAddress((void**)&pwh, g_pwh);

    const int SM128_3 = 2 * (2*128 + 2*128) * AST * (int)sizeof(__half);  // 81920
    const int SM256_1 = 2 * (128 + 256) * AST * (int)sizeof(__half);      // 61440
    const int FSMEM   = (2*128 + 2*4*64) * FST * (int)sizeof(__half);     // 110592
    cudaFuncSetAttribute(sgemm<128,3,true>,  cudaFuncAttributeMaxDynamicSharedMemorySize, SM128_3);
    cudaFuncSetAttribute(sgemm<128,3,false>, cudaFuncAttributeMaxDynamicSharedMemorySize, SM128_3);
    cudaFuncSetAttribute(sgemm<256,1,false>, cudaFuncAttributeMaxDynamicSharedMemorySize, SM256_1);
    cudaFuncSetAttribute(k_flash, cudaFuncAttributeMaxDynamicSharedMemorySize, FSMEM);

    // weight transpose + split (proj: hi only)
    k_wsplit<<<dim3(3*Dz/32, Dz/32, Lz), 256>>>(qkv_w, qkh, qkl, Dz, 3*Dz);
    k_wsplit<<<dim3(Dz/32,   Dz/32, Lz), 256>>>(out_w, owh, owl, Dz, Dz);
    k_wsplit<<<dim3(2*Dz/32, Dz/32, Lz), 256>>>(mlp_w, mwh, mwl, Dz, 2*Dz);
    k_wsplit<<<dim3(Vz/32,   Dz/32, 1),  256>>>(proj_w, pwh, nullptr, Dz, Vz);

    k_embed<<<BSz, 256>>>(tokens, emb, pos, x, xh, xl);

    for (int l = 0; l < Lz; l++) {
        const long long wq = (long long)l * 3*Dz*Dz;
        const long long wo = (long long)l * Dz*Dz;
        const long long wm = (long long)l * 2*Dz*Dz;

        // qkv = x @ qkv_w[l] + b  (3-term; output split hi/lo)
        sgemm<128,3,true><<<dim3(BSz/128, 3*Dz/128), 256, SM128_3>>>(
            xh, xl, Dz, qkh + wq, qkl + wq, Dz,
            nullptr, hh, hl, 3*Dz, qkv_b + (long long)l*3*Dz, Dz);

        // fused causal attention (double-buffered K/V) -> oh/ol
        k_flash<<<dim3(Sz/128, 1, Bz*Hz), 256, FSMEM>>>(hh, hl, oh, ol);

        // o2 = o @ out_w[l] + b  (3-term)
        sgemm<128,3,false><<<dim3(BSz/128, Dz/128), 256, SM128_3>>>(
            oh, ol, Dz, owh + wo, owl + wo, Dz,
            o2, nullptr, nullptr, Dz, out_b + (long long)l*Dz, Dz);

        // x = LN(o2 + x)  (+ split)
        k_add_ln<<<BSz, 256>>>(o2, x, xh, xl,
                               ln1_g + (long long)l*Dz, ln1_b + (long long)l*Dz);

        // h2 = x @ mlp_w[l] + b  (3-term)
        sgemm<128,3,false><<<dim3(BSz/128, 2*Dz/128), 256, SM128_3>>>(
            xh, xl, Dz, mwh + wm, mwl + wm, Dz,
            h2, nullptr, nullptr, 2*Dz, mlp_b + (long long)l*2*Dz, Dz);

        // x = LN(a * gelu(g))  (+ split)
        k_geglu_ln<<<BSz, 256>>>(h2, x, xh, xl,
                                 ln2_g + (long long)l*Dz, ln2_b + (long long)l*Dz);
    }

    // out = x @ proj_w + proj_b  (1-term; BN=256 wide tile)
    sgemm<256,1,false><<<dim3(BSz/128, Vz/256), 256, SM256_1>>>(
        xh, nullptr, Dz, pwh, nullptr, Dz,
        out, nullptr, nullptr, Vz, proj_b, Dz);
}

// round 17
// speedup vs baseline: 1.5322x; 1.5322x over previous
#include <cuda_runtime.h>
#include <cuda_fp16.h>
#include <math.h>

// Problem constants
#define Bz   2
#define Sz   1024
#define Dz   1024
#define Hz   16
#define Lz   4
#define Vz   32000
#define DKz  64
#define BSz  (Bz*Sz)   // 2048

#define AST  40        // smem k-stride (halves): 80B rows, LDSM conflict-free
#define FST  72        // flash smem stride (halves): 144B rows, LDSM conflict-free

// ---------------------------------------------------------------------------
// Scratch (static device globals; no allocation anywhere)
// ---------------------------------------------------------------------------
__device__ __align__(256) float  g_x [BSz*Dz];
__device__ __align__(256) __half g_xh[BSz*Dz];
__device__ __align__(256) __half g_xl[BSz*Dz];
__device__ __align__(256) __half g_hh[(long long)BSz*3*Dz];   // qkv split hi
__device__ __align__(256) __half g_hl[(long long)BSz*3*Dz];   // qkv split lo
__device__ __align__(256) __half g_oh[BSz*Dz];
__device__ __align__(256) __half g_ol[BSz*Dz];
__device__ __align__(256) float  g_o2[BSz*Dz];
__device__ __align__(256) float  g_h2[BSz*2*Dz];
// weight hi/lo, TRANSPOSED to [N][K]
__device__ __align__(256) __half g_qkh[(long long)Lz*3*Dz*Dz];
__device__ __align__(256) __half g_qkl[(long long)Lz*3*Dz*Dz];
__device__ __align__(256) __half g_owh[(long long)Lz*Dz*Dz];
__device__ __align__(256) __half g_owl[(long long)Lz*Dz*Dz];
__device__ __align__(256) __half g_mwh[(long long)Lz*2*Dz*Dz];
__device__ __align__(256) __half g_mwl[(long long)Lz*2*Dz*Dz];
__device__ __align__(256) __half g_pwh[(long long)Vz*Dz];   // proj: hi only

// ---------------------------------------------------------------------------
// helpers
// ---------------------------------------------------------------------------
__device__ __forceinline__ void split1(float v, __half& h, __half& l)
{
    h = __float2half_rn(v);
    l = __float2half_rn(v - __half2float(h));
}
__device__ __forceinline__ unsigned packh2(__half a, __half b)
{
    __half2 t = __halves2half2(a, b);
    return *reinterpret_cast<unsigned*>(&t);
}
__device__ __forceinline__ void cpa16(void* dst, const void* src)
{
    unsigned d = (unsigned)__cvta_generic_to_shared(dst);
    asm volatile("cp.async.cg.shared.global [%0], [%1], 16;\n" :: "r"(d), "l"(src));
}
__device__ __forceinline__ void cpcommit()
{
    asm volatile("cp.async.commit_group;\n");
}
__device__ __forceinline__ void mma16816(float* c, const unsigned* a, const unsigned* b)
{
    asm volatile(
        "mma.sync.aligned.m16n8k16.row.col.f32.f16.f16.f32 "
        "{%0,%1,%2,%3}, {%4,%5,%6,%7}, {%8,%9}, {%0,%1,%2,%3};\n"
        : "+f"(c[0]), "+f"(c[1]), "+f"(c[2]), "+f"(c[3])
        : "r"(a[0]), "r"(a[1]), "r"(a[2]), "r"(a[3]), "r"(b[0]), "r"(b[1]));
}
__device__ __forceinline__ void ldsm4(unsigned* r, const void* p)
{
    unsigned a = (unsigned)__cvta_generic_to_shared(p);
    asm volatile("ldmatrix.sync.aligned.m8n8.x4.shared.b16 {%0,%1,%2,%3}, [%4];\n"
        : "=r"(r[0]), "=r"(r[1]), "=r"(r[2]), "=r"(r[3]) : "r"(a));
}
__device__ __forceinline__ void ldsm4t(unsigned* r, const void* p)
{
    unsigned a = (unsigned)__cvta_generic_to_shared(p);
    asm volatile("ldmatrix.sync.aligned.m8n8.x4.trans.shared.b16 {%0,%1,%2,%3}, [%4];\n"
        : "=r"(r[0]), "=r"(r[1]), "=r"(r[2]), "=r"(r[3]) : "r"(a));
}
__device__ __forceinline__ float warp8_sum(float v, float* red, int tid)
{
    #pragma unroll
    for (int o = 16; o; o >>= 1) v += __shfl_xor_sync(0xffffffffu, v, o);
    if ((tid & 31) == 0) red[tid >> 5] = v;
    __syncthreads();
    float r = (red[0] + red[1]) + (red[2] + red[3])
            + (red[4] + red[5]) + (red[6] + red[7]);
    __syncthreads();
    return r;
}

// ---------------------------------------------------------------------------
// Weight transpose + split: W[K,N] f32 -> T_hi (+T_lo) [N,K].
// Packed uint2 stores on the transposed side (4 halves per store).
// ---------------------------------------------------------------------------
__global__ void __launch_bounds__(256)
k_wsplit(const float* __restrict__ W, __half* __restrict__ Th, __half* __restrict__ Tl,
         int K, int N)
{
    __shared__ float t[32][33];
    const long long zo = (long long)blockIdx.z * K * N;
    W  += zo; Th += zo; if (Tl) Tl += zo;
    const int n0 = blockIdx.x * 32, k0 = blockIdx.y * 32;
    const int tid = threadIdx.x;
    const int tx = tid & 31, ty = tid >> 5;
    #pragma unroll
    for (int p = 0; p < 4; p++)
        t[ty + 8*p][tx] = W[(long long)(k0 + ty + 8*p) * N + n0 + tx];
    __syncthreads();

    // packed write: thread -> (n = tid>>3, k group = (tid&7)*4)
    const int n  = tid >> 3;
    const int kg = (tid & 7) * 4;
    float v0 = t[kg    ][n], v1 = t[kg + 1][n];
    float v2 = t[kg + 2][n], v3 = t[kg + 3][n];
    __half h0,l0,h1,l1,h2,l2,h3,l3;
    split1(v0,h0,l0); split1(v1,h1,l1); split1(v2,h2,l2); split1(v3,h3,l3);
    const long long o = (long long)(n0 + n) * K + k0 + kg;
    *(uint2*)&Th[o] = make_uint2(packh2(h0,h1), packh2(h2,h3));
    if (Tl) *(uint2*)&Tl[o] = make_uint2(packh2(l0,l1), packh2(l2,l3));
}

// ---------------------------------------------------------------------------
// Embedding (writes float + hi/lo)
// ---------------------------------------------------------------------------
__global__ void k_embed(const int* __restrict__ tok,
                        const float* __restrict__ emb,
                        const float* __restrict__ pos,
                        float* __restrict__ x,
                        __half* __restrict__ xh, __half* __restrict__ xl)
{
    int row = blockIdx.x;
    int s   = row % Sz;
    long long t = tok[row];
    const float* e = emb + t * Dz;
    const float* p = pos + (long long)s * Dz;
    long long o = (long long)row * Dz;
    for (int d = threadIdx.x; d < Dz; d += blockDim.x) {
        float v = e[d] + p[d];
        x[o + d] = v;
        __half h, l; split1(v, h, l);
        xh[o + d] = h; xl[o + d] = l;
    }
}

// ---------------------------------------------------------------------------
// Fused flash attention (causal). One CTA = 128 q-rows of one (batch, head).
// Pre-split inputs; pure-copy smem fills; PV via ldmatrix.trans.
// Single-buffer K/V (73.7 KB smem -> 2 CTA/SM; R16 double-buffer regressed).
// ---------------------------------------------------------------------------
__global__ void __launch_bounds__(256)
k_flash(const __half* __restrict__ Hh, const __half* __restrict__ Hl,
        __half* __restrict__ Oh, __half* __restrict__ Ol)
{
    const int z = blockIdx.z, b = z >> 4, head = z & 15;
    const int bx = blockIdx.x;
    const int qt = (bx < 4) ? (7 - bx) : (bx - 4);   // pair-balanced map
    const int bq = qt * 128;

    extern __shared__ __half fsm[];
    __half (*Qh)[FST]  = (__half(*)[FST])fsm;
    __half (*Ql)[FST]  = Qh  + 128;
    __half (*Kh)[FST]  = Ql  + 128;
    __half (*Kl)[FST]  = Kh  + 64;
    __half (*Vsh)[FST] = Kl  + 64;   // V: [key][dk]
    __half (*Vsl)[FST] = Vsh + 64;

    const int tid = threadIdx.x, warp = tid >> 5, lane = tid & 31;
    const int g = lane >> 2, tg = lane & 3;
    const int lrow = lane & 15, lk = (lane >> 4) << 3;

    const long long base = (long long)b * Sz * 3 * Dz + head * DKz;
    const __half* Qgh = Hh + base;
    const __half* Qgl = Hl + base;
    const __half* Kgh = Qgh + Dz;
    const __half* Kgl = Qgl + Dz;
    const __half* Vgh = Qgh + 2 * Dz;
    const __half* Vgl = Qgl + 2 * Dz;

    #pragma unroll
    for (int i = 0; i < 4; i++) {
        int u = tid + i * 256;
        int r = u >> 3, j = u & 7;
        long long off = (long long)(bq + r) * 3 * Dz + 8 * j;
        cpa16(&Qh[r][8 * j], Qgh + off);
        cpa16(&Ql[r][8 * j], Qgl + off);
    }

    float m0 = -1e30f, m1 = -1e30f, l0s = 0.f, l1s = 0.f;
    float acc[8][4];
    #pragma unroll
    for (int nt = 0; nt < 8; nt++)
        #pragma unroll
        for (int i = 0; i < 4; i++) acc[nt][i] = 0.f;

    const int r0 = bq + warp * 16 + g, r1 = r0 + 8;
    const int KTILES = 2 * qt + 2;

    for (int kt = 0; kt < KTILES; kt++) {
        const int bk = kt * 64;
        __syncthreads();

        #pragma unroll
        for (int i = 0; i < 2; i++) {
            int u = tid + i * 256;
            int r = u >> 3, j = u & 7;
            long long off = (long long)(bk + r) * 3 * Dz + 8 * j;
            cpa16(&Kh[r][8 * j],  Kgh + off);
            cpa16(&Kl[r][8 * j],  Kgl + off);
            cpa16(&Vsh[r][8 * j], Vgh + off);
            cpa16(&Vsl[r][8 * j], Vgl + off);
        }
        cpcommit();
        asm volatile("cp.async.wait_group 0;\n");
        __syncthreads();

        // S = Q K^T (3-term split)
        float s[8][4];
        #pragma unroll
        for (int nt = 0; nt < 8; nt++)
            #pragma unroll
            for (int i = 0; i < 4; i++) s[nt][i] = 0.f;

        #pragma unroll
        for (int c = 0; c < 4; c++) {
            unsigned ah[4], al[4], bh[8][2], bl[8][2];
            ldsm4(ah, &Qh[warp*16 + lrow][c*16 + lk]);
            ldsm4(al, &Ql[warp*16 + lrow][c*16 + lk]);
            #pragma unroll
            for (int ng = 0; ng < 4; ng++) {
                unsigned q[4];
                ldsm4(q, &Kh[ng*16 + lrow][c*16 + lk]);
                bh[2*ng][0]=q[0]; bh[2*ng+1][0]=q[1]; bh[2*ng][1]=q[2]; bh[2*ng+1][1]=q[3];
                ldsm4(q, &Kl[ng*16 + lrow][c*16 + lk]);
                bl[2*ng][0]=q[0]; bl[2*ng+1][0]=q[1]; bl[2*ng][1]=q[2]; bl[2*ng+1][1]=q[3];
            }
            #pragma unroll
            for (int nt = 0; nt < 8; nt++) {
                mma16816(s[nt], ah, bh[nt]);
                mma16816(s[nt], ah, bl[nt]);
                mma16816(s[nt], al, bh[nt]);
            }
        }

        if (kt >= 2*qt) {
            #pragma unroll
            for (int nt = 0; nt < 8; nt++) {
                int c0 = bk + nt*8 + 2*tg, c1 = c0 + 1;
                s[nt][0] = (c0 <= r0) ? s[nt][0]*0.125f : -1e30f;
                s[nt][1] = (c1 <= r0) ? s[nt][1]*0.125f : -1e30f;
                s[nt][2] = (c0 <= r1) ? s[nt][2]*0.125f : -1e30f;
                s[nt][3] = (c1 <= r1) ? s[nt][3]*0.125f : -1e30f;
            }
        } else {
            #pragma unroll
            for (int nt = 0; nt < 8; nt++)
                #pragma unroll
                for (int i = 0; i < 4; i++) s[nt][i] *= 0.125f;
        }

        float tm0 = -1e30f, tm1 = -1e30f;
        #pragma unroll
        for (int nt = 0; nt < 8; nt++) {
            tm0 = fmaxf(tm0, fmaxf(s[nt][0], s[nt][1]));
            tm1 = fmaxf(tm1, fmaxf(s[nt][2], s[nt][3]));
        }
        tm0 = fmaxf(tm0, __shfl_xor_sync(0xffffffffu, tm0, 1));
        tm0 = fmaxf(tm0, __shfl_xor_sync(0xffffffffu, tm0, 2));
        tm1 = fmaxf(tm1, __shfl_xor_sync(0xffffffffu, tm1, 1));
        tm1 = fmaxf(tm1, __shfl_xor_sync(0xffffffffu, tm1, 2));
        const float mn0 = fmaxf(m0, tm0), mn1 = fmaxf(m1, tm1);
        const float al0 = __expf(m0 - mn0), al1 = __expf(m1 - mn1);

        float rs0 = 0.f, rs1 = 0.f;
        unsigned pa[4][4];
        #pragma unroll
        for (int c = 0; c < 4; c++) {
            float p00 = __expf(s[2*c  ][0] - mn0), p01 = __expf(s[2*c  ][1] - mn0);
            float p10 = __expf(s[2*c  ][2] - mn1), p11 = __expf(s[2*c  ][3] - mn1);
            float p02 = __expf(s[2*c+1][0] - mn0), p03 = __expf(s[2*c+1][1] - mn0);
            float p12 = __expf(s[2*c+1][2] - mn1), p13 = __expf(s[2*c+1][3] - mn1);
            rs0 += (p00 + p01) + (p02 + p03);
            rs1 += (p10 + p11) + (p12 + p13);
            pa[c][0] = packh2(__float2half_rn(p00), __float2half_rn(p01));
            pa[c][1] = packh2(__float2half_rn(p10), __float2half_rn(p11));
            pa[c][2] = packh2(__float2half_rn(p02), __float2half_rn(p03));
            pa[c][3] = packh2(__float2half_rn(p12), __float2half_rn(p13));
        }
        rs0 += __shfl_xor_sync(0xffffffffu, rs0, 1);
        rs0 += __shfl_xor_sync(0xffffffffu, rs0, 2);
        rs1 += __shfl_xor_sync(0xffffffffu, rs1, 1);
        rs1 += __shfl_xor_sync(0xffffffffu, rs1, 2);
        l0s = l0s * al0 + rs0;
        l1s = l1s * al1 + rs1;
        m0 = mn0; m1 = mn1;

        #pragma unroll
        for (int nt = 0; nt < 8; nt++) {
            acc[nt][0] *= al0; acc[nt][1] *= al0;
            acc[nt][2] *= al1; acc[nt][3] *= al1;
        }

        #pragma unroll
        for (int c = 0; c < 4; c++) {
            unsigned bh[8][2], bl[8][2];
            #pragma unroll
            for (int ng = 0; ng < 4; ng++) {
                unsigned q[4];
                ldsm4t(q, &Vsh[c*16 + lrow][ng*16 + lk]);
                bh[2*ng][0]=q[0]; bh[2*ng][1]=q[1]; bh[2*ng+1][0]=q[2]; bh[2*ng+1][1]=q[3];
                ldsm4t(q, &Vsl[c*16 + lrow][ng*16 + lk]);
                bl[2*ng][0]=q[0]; bl[2*ng][1]=q[1]; bl[2*ng+1][0]=q[2]; bl[2*ng+1][1]=q[3];
            }
            #pragma unroll
            for (int nt = 0; nt < 8; nt++) {
                mma16816(acc[nt], pa[c], bh[nt]);
                mma16816(acc[nt], pa[c], bl[nt]);
            }
        }
    }

    const float il0 = 1.f / l0s, il1 = 1.f / l1s;
    const long long gr0 = (long long)b * Sz + r0;
    const long long gr1 = gr0 + 8;
    #pragma unroll
    for (int nt = 0; nt < 8; nt++) {
        int col = head * 64 + nt * 8 + 2 * tg;
        __half h0, lo0, h1, lo1;
        split1(acc[nt][0] * il0, h0, lo0); split1(acc[nt][1] * il0, h1, lo1);
        *(unsigned*)&Oh[gr0 * Dz + col] = packh2(h0, h1);
        *(unsigned*)&Ol[gr0 * Dz + col] = packh2(lo0, lo1);
        split1(acc[nt][2] * il1, h0, lo0); split1(acc[nt][3] * il1, h1, lo1);
        *(unsigned*)&Oh[gr1 * Dz + col] = packh2(h0, h1);
        *(unsigned*)&Ol[gr1 * Dz + col] = packh2(lo0, lo1);
    }
}

// ---------------------------------------------------------------------------
// Split-fp16 GEMM: ldmatrix fragments, 2-stage cp.async pipeline.
// TERMS=3: Ah*Bh + Ah*Bl + Al*Bh.  TERMS=1: Ah*Bh.
// OUTH: write split hi/lo (Ch/Cl) instead of float Cf.
// ---------------------------------------------------------------------------
template<int BN, int TERMS, bool OUTH>
__global__ void __launch_bounds__(256)
sgemm(const __half* __restrict__ Ah, const __half* __restrict__ Al, int lda,
      const __half* __restrict__ Bh, const __half* __restrict__ Bl, int ldb,
      float* __restrict__ Cf, __half* __restrict__ Ch, __half* __restrict__ Cl,
      int ldc, const float* __restrict__ bias, int K)
{
    constexpr int BM = 128, BK = 32;
    constexpr int WN = BN / 2;
    constexpr int NT = WN / 8;
    constexpr int NG = WN / 16;
    constexpr int STG = (TERMS == 3 ? (2*BM + 2*BN) : (BM + BN)) * AST;

    extern __shared__ __half smem_dyn[];

    const int bm = blockIdx.x * BM;
    const int bn = blockIdx.y * BN;
    const int tid = threadIdx.x, warp = tid >> 5, lane = tid & 31;
    const int g = lane >> 2, tg = lane & 3;
    const int wm = warp >> 1, wn = warp & 1;
    const int lrow = lane & 15;
    const int lk   = (lane >> 4) << 3;

    const int KT = K / BK;

    float acc[2][NT][4];
    #pragma unroll
    for (int mt = 0; mt < 2; mt++)
        #pragma unroll
        for (int nt = 0; nt < NT; nt++)
            #pragma unroll
            for (int i = 0; i < 4; i++) acc[mt][nt][i] = 0.f;

    auto fill = [&](int st, int k0) {
        __half* sa_h = smem_dyn + st * STG;
        __half* sa_l = sa_h + BM * AST;
        __half* sb_h = sa_h + (TERMS == 3 ? 2 : 1) * BM * AST;
        __half* sb_l = sb_h + BN * AST;
        #pragma unroll
        for (int i = 0; i < (BM * BK / 8) / 256; i++) {
            int u = tid + i * 256;
            int row = u >> 2, j = u & 3;
            long long off = (long long)(bm + row) * lda + k0 + 8 * j;
            cpa16(sa_h + row * AST + 8 * j, Ah + off);
            if (TERMS == 3) cpa16(sa_l + row * AST + 8 * j, Al + off);
        }
        #pragma unroll
        for (int i = 0; i < (BN * BK / 8) / 256; i++) {
            int u = tid + i * 256;
            int row = u >> 2, j = u & 3;
            long long off = (long long)(bn + row) * ldb + k0 + 8 * j;
            cpa16(sb_h + row * AST + 8 * j, Bh + off);
            if (TERMS == 3) cpa16(sb_l + row * AST + 8 * j, Bl + off);
        }
    };

    fill(0, 0);
    cpcommit();

    for (int kt = 0; kt < KT; kt++) {
        const int st = kt & 1;
        if (kt + 1 < KT) fill(st ^ 1, (kt + 1) * BK);
        cpcommit();
        asm volatile("cp.async.wait_group 1;\n");
        __syncthreads();

        const __half* sa_h = smem_dyn + st * STG;
        const __half* sa_l = sa_h + BM * AST;
        const __half* sb_h = sa_h + (TERMS == 3 ? 2 : 1) * BM * AST;
        const __half* sb_l = sb_h + BN * AST;

        #pragma unroll
        for (int ks = 0; ks < BK; ks += 16) {
            unsigned ah[2][4], al[2][4], bh[NT][2], bl[NT][2];
            #pragma unroll
            for (int mt = 0; mt < 2; mt++) {
                const int r = wm * 32 + mt * 16 + lrow;
                ldsm4(ah[mt], sa_h + r * AST + ks + lk);
                if (TERMS == 3) ldsm4(al[mt], sa_l + r * AST + ks + lk);
            }
            #pragma unroll
            for (int ng = 0; ng < NG; ng++) {
                const int c = wn * WN + ng * 16 + lrow;
                unsigned q[4];
                ldsm4(q, sb_h + c * AST + ks + lk);
                bh[2*ng][0] = q[0]; bh[2*ng+1][0] = q[1];
                bh[2*ng][1] = q[2]; bh[2*ng+1][1] = q[3];
                if (TERMS == 3) {
                    ldsm4(q, sb_l + c * AST + ks + lk);
                    bl[2*ng][0] = q[0]; bl[2*ng+1][0] = q[1];
                    bl[2*ng][1] = q[2]; bl[2*ng+1][1] = q[3];
                }
            }
            #pragma unroll
            for (int mt = 0; mt < 2; mt++)
                #pragma unroll
                for (int nt = 0; nt < NT; nt++) {
                    mma16816(acc[mt][nt], ah[mt], bh[nt]);
                    if (TERMS == 3) {
                        mma16816(acc[mt][nt], ah[mt], bl[nt]);
                        mma16816(acc[mt][nt], al[mt], bh[nt]);
                    }
                }
        }
        __syncthreads();
    }

    #pragma unroll
    for (int nt = 0; nt < NT; nt++) {
        int col = bn + wn * WN + nt * 8 + 2 * tg;
        float2 bv = *(const float2*)&bias[col];
        #pragma unroll
        for (int mt = 0; mt < 2; mt++) {
            int row = bm + wm * 32 + mt * 16 + g;
            float v00 = acc[mt][nt][0] + bv.x, v01 = acc[mt][nt][1] + bv.y;
            float v10 = acc[mt][nt][2] + bv.x, v11 = acc[mt][nt][3] + bv.y;
            if (OUTH) {
                __half h0, h1, l0, l1;
                split1(v00, h0, l0); split1(v01, h1, l1);
                *(unsigned*)&Ch[(long long)row * ldc + col] = packh2(h0, h1);
                *(unsigned*)&Cl[(long long)row * ldc + col] = packh2(l0, l1);
                split1(v10, h0, l0); split1(v11, h1, l1);
                *(unsigned*)&Ch[(long long)(row + 8) * ldc + col] = packh2(h0, h1);
                *(unsigned*)&Cl[(long long)(row + 8) * ldc + col] = packh2(l0, l1);
            } else {
                *(float2*)&Cf[(long long)row * ldc + col] = make_float2(v00, v01);
                *(float2*)&Cf[(long long)(row + 8) * ldc + col] = make_float2(v10, v11);
            }
        }
    }
}

// ---------------------------------------------------------------------------
// Vectorized LN kernels: 1024 = 256 threads x float4, values in registers.
// ---------------------------------------------------------------------------
__global__ void __launch_bounds__(256)
k_add_ln(const float* __restrict__ a, float* __restrict__ x,
         __half* __restrict__ xh, __half* __restrict__ xl,
         const float* __restrict__ gam, const float* __restrict__ bet)
{
    const long long row = blockIdx.x;
    const int tid = threadIdx.x;
    __shared__ float red[8];

    const float4* a4 = (const float4*)(a + row * Dz);
    float4*       x4 = (float4*)(x + row * Dz);

    float4 av = a4[tid], xv = x4[tid];
    float4 v;
    v.x = av.x + xv.x; v.y = av.y + xv.y; v.z = av.z + xv.z; v.w = av.w + xv.w;

    float s = (v.x + v.y) + (v.z + v.w);
    const float mean = warp8_sum(s, red, tid) * (1.f / Dz);

    float dx = v.x - mean, dy = v.y - mean, dz = v.z - mean, dw = v.w - mean;
    float s2 = (dx*dx + dy*dy) + (dz*dz + dw*dw);
    const float var = warp8_sum(s2, red, tid) * (1.f / Dz);
    const float inv = rsqrtf(var + 1e-5f);

    float4 gv = *(const float4*)(gam + tid*4);
    float4 bv = *(const float4*)(bet + tid*4);
    float4 y;
    y.x = dx * inv * gv.x + bv.x;
    y.y = dy * inv * gv.y + bv.y;
    y.z = dz * inv * gv.z + bv.z;
    y.w = dw * inv * gv.w + bv.w;
    x4[tid] = y;

    __half h0,l0,h1,l1,h2,l2,h3,l3;
    split1(y.x,h0,l0); split1(y.y,h1,l1); split1(y.z,h2,l2); split1(y.w,h3,l3);
    *(uint2*)&xh[row * Dz + tid*4] = make_uint2(packh2(h0,h1), packh2(h2,h3));
    *(uint2*)&xl[row * Dz + tid*4] = make_uint2(packh2(l0,l1), packh2(l2,l3));
}

__global__ void __launch_bounds__(256)
k_geglu_ln(const float* __restrict__ h2, float* __restrict__ x,
           __half* __restrict__ xh, __half* __restrict__ xl,
           const float* __restrict__ gam, const float* __restrict__ bet)
{
    const long long row = blockIdx.x;
    const int tid = threadIdx.x;
    __shared__ float red[8];

    const float4* a4 = (const float4*)(h2 + row * 2 * Dz);
    const float4* g4 = (const float4*)(h2 + row * 2 * Dz + Dz);

    float4 av = a4[tid], gg = g4[tid];
    float4 v;
    v.x = av.x * (0.5f * gg.x * (1.f + erff(gg.x * 0.70710678118654752f)));
    v.y = av.y * (0.5f * gg.y * (1.f + erff(gg.y * 0.70710678118654752f)));
    v.z = av.z * (0.5f * gg.z * (1.f + erff(gg.z * 0.70710678118654752f)));
    v.w = av.w * (0.5f * gg.w * (1.f + erff(gg.w * 0.70710678118654752f)));

    float s = (v.x + v.y) + (v.z + v.w);
    const float mean = warp8_sum(s, red, tid) * (1.f / Dz);

    float dx = v.x - mean, dy = v.y - mean, dz = v.z - mean, dw = v.w - mean;
    float s2 = (dx*dx + dy*dy) + (dz*dz + dw*dw);
    const float var = warp8_sum(s2, red, tid) * (1.f / Dz);
    const float inv = rsqrtf(var + 1e-5f);

    float4 gv = *(const float4*)(gam + tid*4);
    float4 bv = *(const float4*)(bet + tid*4);
    float4 y;
    y.x = dx * inv * gv.x + bv.x;
    y.y = dy * inv * gv.y + bv.y;
    y.z = dz * inv * gv.z + bv.z;
    y.w = dw * inv * gv.w + bv.w;
    *(float4*)(x + row * Dz + tid*4) = y;

    __half h0,l0,h1,l1,h2_,l2,h3,l3;
    split1(y.x,h0,l0); split1(y.y,h1,l1); split1(y.z,h2_,l2); split1(y.w,h3,l3);
    *(uint2*)&xh[row * Dz + tid*4] = make_uint2(packh2(h0,h1), packh2(h2_,h3));
    *(uint2*)&xl[row * Dz + tid*4] = make_uint2(packh2(l0,l1), packh2(l2,l3));
}

// ---------------------------------------------------------------------------
// Driver
// ---------------------------------------------------------------------------
extern "C" void kernel_launch(void* const* d_in, const int* in_sizes, int n_in,
                              void* d_out, int out_size)
{
    (void)in_sizes; (void)n_in; (void)out_size;
    const int*   tokens = (const int*)  d_in[0];
    const float* emb    = (const float*)d_in[2];
    const float* pos    = (const float*)d_in[3];
    const float* qkv_w  = (const float*)d_in[4];
    const float* qkv_b  = (const float*)d_in[5];
    const float* out_w  = (const float*)d_in[6];
    const float* out_b  = (const float*)d_in[7];
    const float* ln1_g  = (const float*)d_in[8];
    const float* ln1_b  = (const float*)d_in[9];
    const float* mlp_w  = (const float*)d_in[10];
    const float* mlp_b  = (const float*)d_in[11];
    const float* ln2_g  = (const float*)d_in[12];
    const float* ln2_b  = (const float*)d_in[13];
    const float* proj_w = (const float*)d_in[14];
    const float* proj_b = (const float*)d_in[15];
    float* out = (float*)d_out;

    float *x, *o2, *h2;
    __half *xh, *xl, *hh, *hl, *oh, *ol;
    __half *qkh, *qkl, *owh, *owl, *mwh, *mwl, *pwh;
    cudaGetSymbolAddress((void**)&x,  g_x);
    cudaGetSymbolAddress((void**)&xh, g_xh);
    cudaGetSymbolAddress((void**)&xl, g_xl);
    cudaGetSymbolAddress((void**)&hh, g_hh);
    cudaGetSymbolAddress((void**)&hl, g_hl);
    cudaGetSymbolAddress((void**)&oh, g_oh);
    cudaGetSymbolAddress((void**)&ol, g_ol);
    cudaGetSymbolAddress((void**)&o2, g_o2);
    cudaGetSymbolAddress((void**)&h2, g_h2);
    cudaGetSymbolAddress((void**)&qkh, g_qkh);
    cudaGetSymbolAddress((void**)&qkl, g_qkl);
    cudaGetSymbolAddress((void**)&owh, g_owh);
    cudaGetSymbolAddress((void**)&owl, g_owl);
    cudaGetSymbolAddress((void**)&mwh, g_mwh);
    cudaGetSymbolAddress((void**)&mwl, g_mwl);
    cudaGetSymbolAddress((void**)&pwh, g_pwh);

    const int SM128_3 = 2 * (2*128 + 2*128) * AST * (int)sizeof(__half);  // 81920
    const int SM256_1 = 2 * (128 + 256) * AST * (int)sizeof(__half);      // 61440
    const int FSMEM   = (2*128 + 4*64) * FST * (int)sizeof(__half);       // 73728
    cudaFuncSetAttribute(sgemm<128,3,true>,  cudaFuncAttributeMaxDynamicSharedMemorySize, SM128_3);
    cudaFuncSetAttribute(sgemm<128,3,false>, cudaFuncAttributeMaxDynamicSharedMemorySize, SM128_3);
    cudaFuncSetAttribute(sgemm<256,1,false>, cudaFuncAttributeMaxDynamicSharedMemorySize, SM256_1);
    cudaFuncSetAttribute(k_flash, cudaFuncAttributeMaxDynamicSharedMemorySize, FSMEM);

    // weight transpose + split (proj: hi only)
    k_wsplit<<<dim3(3*Dz/32, Dz/32, Lz), 256>>>(qkv_w, qkh, qkl, Dz, 3*Dz);
    k_wsplit<<<dim3(Dz/32,   Dz/32, Lz), 256>>>(out_w, owh, owl, Dz, Dz);
    k_wsplit<<<dim3(2*Dz/32, Dz/32, Lz), 256>>>(mlp_w, mwh, mwl, Dz, 2*Dz);
    k_wsplit<<<dim3(Vz/32,   Dz/32, 1),  256>>>(proj_w, pwh, nullptr, Dz, Vz);

    k_embed<<<BSz, 256>>>(tokens, emb, pos, x, xh, xl);

    for (int l = 0; l < Lz; l++) {
        const long long wq = (long long)l * 3*Dz*Dz;
        const long long wo = (long long)l * Dz*Dz;
        const long long wm = (long long)l * 2*Dz*Dz;

        // qkv = x @ qkv_w[l] + b  (3-term; output split hi/lo)
        sgemm<128,3,true><<<dim3(BSz/128, 3*Dz/128), 256, SM128_3>>>(
            xh, xl, Dz, qkh + wq, qkl + wq, Dz,
            nullptr, hh, hl, 3*Dz, qkv_b + (long long)l*3*Dz, Dz);

        // fused causal attention -> oh/ol
        k_flash<<<dim3(Sz/128, 1, Bz*Hz), 256, FSMEM>>>(hh, hl, oh, ol);

        // o2 = o @ out_w[l] + b  (3-term)
        sgemm<128,3,false><<<dim3(BSz/128, Dz/128), 256, SM128_3>>>(
            oh, ol, Dz, owh + wo, owl + wo, Dz,
            o2, nullptr, nullptr, Dz, out_b + (long long)l*Dz, Dz);

        // x = LN(o2 + x)  (+ split)
        k_add_ln<<<BSz, 256>>>(o2, x, xh, xl,
                               ln1_g + (long long)l*Dz, ln1_b + (long long)l*Dz);

        // h2 = x @ mlp_w[l] + b  (3-term)
        sgemm<128,3,false><<<dim3(BSz/128, 2*Dz/128), 256, SM128_3>>>(
            xh, xl, Dz, mwh + wm, mwl + wm, Dz,
            h2, nullptr, nullptr, 2*Dz, mlp_b + (long long)l*2*Dz, Dz);

        // x = LN(a * gelu(g))  (+ split)
        k_geglu_ln<<<BSz, 256>>>(h2, x, xh, xl,
                                 ln2_g + (long long)l*Dz, ln2_b + (long long)l*Dz);
    }

    // out = x @ proj_w + proj_b  (1-term; BN=256 wide tile)
    sgemm<256,1,false><<<dim3(BSz/128, Vz/256), 256, SM256_1>>>(
        xh, nullptr, Dz, pwh, nullptr, Dz,
        out, nullptr, nullptr, Vz, proj_b, Dz);
}